// round 1
// baseline (speedup 1.0000x reference)
#include <cuda_runtime.h>
#include <cuda_bf16.h>

#define BATCH 2
#define CH 512
#define FH 50
#define FW 75
#define HW (FH * FW)          // 3750
#define PH 8
#define PW 8
#define SPATIAL_SCALE (1.0f / 16.0f)

// NHWC scratch: 2 * 3750 * 512 floats = 15.36 MB (fits L2)
__device__ float g_feat_hwc[BATCH * HW * CH];

// ---------------------------------------------------------------------------
// Kernel 1: NCHW -> NHWC transpose.  Per batch: (C=512, HW=3750) -> (HW, C).
// Tiled 32x32 smem transpose, block (32,8).
// ---------------------------------------------------------------------------
__global__ void transpose_nchw_nhwc(const float* __restrict__ in) {
    __shared__ float tile[32][33];
    const int b   = blockIdx.z;
    const int hw0 = blockIdx.x * 32;
    const int c0  = blockIdx.y * 32;

    const float* src = in + (size_t)b * CH * HW;
    float*       dst = g_feat_hwc + (size_t)b * HW * CH;

    #pragma unroll
    for (int t = 0; t < 32; t += 8) {
        int c  = c0 + threadIdx.y + t;
        int hw = hw0 + threadIdx.x;
        if (hw < HW)  // c0+31 < 512 always (512 % 32 == 0)
            tile[threadIdx.y + t][threadIdx.x] = src[(size_t)c * HW + hw];
    }
    __syncthreads();
    #pragma unroll
    for (int t = 0; t < 32; t += 8) {
        int hw = hw0 + threadIdx.y + t;
        int c  = c0 + threadIdx.x;
        if (hw < HW)
            dst[(size_t)hw * CH + c] = tile[threadIdx.x][threadIdx.y + t];
    }
}

// ---------------------------------------------------------------------------
// Kernel 2: one CTA per roi, 512 threads = one channel each.
// Computes 8x8 bilinear samples row-by-row (two register rows), fuses the
// 2x2 average pool, writes (C,7,7) per roi.
// ---------------------------------------------------------------------------
__global__ __launch_bounds__(CH, 2)
void roi_plus_avg_kernel(const float* __restrict__ rois,
                         float* __restrict__ out) {
    const int n = blockIdx.x;
    const int c = threadIdx.x;

    __shared__ int   s_hs[PH], s_ws[PW];
    __shared__ float s_hr[PH], s_wr[PW];
    __shared__ int   s_hv[PH], s_wv[PW];
    __shared__ int   s_b;

    if (threadIdx.x < PH) {
        const int i = threadIdx.x;
        const float x1 = rois[n * 5 + 1] * SPATIAL_SCALE;
        const float y1 = rois[n * 5 + 2] * SPATIAL_SCALE;
        const float x2 = rois[n * 5 + 3] * SPATIAL_SCALE;
        const float y2 = rois[n * 5 + 4] * SPATIAL_SCALE;
        const float roi_w = fmaxf(x2 - x1 + 1.0f, 0.0f);
        const float roi_h = fmaxf(y2 - y1 + 1.0f, 0.0f);
        const float bin_h = roi_h * (1.0f / (PH - 1));
        const float bin_w = roi_w * (1.0f / (PW - 1));

        const float hh = y1 + (float)i * bin_h;
        const float ww = x1 + (float)i * bin_w;

        s_hv[i] = (hh >= 0.0f) && (hh < (float)FH);
        s_wv[i] = (ww >= 0.0f) && (ww < (float)FW);

        int hs = (int)floorf(hh);
        int ws = (int)floorf(ww);
        hs = min(max(hs, 0), FH - 2);
        ws = min(max(ws, 0), FW - 2);
        s_hs[i] = hs;
        s_ws[i] = ws;
        s_hr[i] = hh - (float)hs;
        s_wr[i] = ww - (float)ws;

        if (i == 0) s_b = (int)rois[n * 5 + 0];
    }
    __syncthreads();

    const float* fb = g_feat_hwc + (size_t)s_b * HW * CH + c;

    float prev[PW];
    float cur[PW];

    #pragma unroll
    for (int i = 0; i < PH; i++) {
        const int   hs = s_hs[i];
        const float hr = s_hr[i];
        const bool  hv = (s_hv[i] != 0);
        const float* r0 = fb + (size_t)(hs * FW) * CH;
        const float* r1 = r0 + (size_t)FW * CH;

        #pragma unroll
        for (int j = 0; j < PW; j++) {
            float v = 0.0f;
            if (hv && s_wv[j]) {
                const int   ws = s_ws[j];
                const float wr = s_wr[j];
                const float ul = __ldg(r0 + (size_t)ws * CH);
                const float ur = __ldg(r0 + (size_t)(ws + 1) * CH);
                const float ll = __ldg(r1 + (size_t)ws * CH);
                const float lr = __ldg(r1 + (size_t)(ws + 1) * CH);
                const float top = fmaf(ur - ul, wr, ul);
                const float bot = fmaf(lr - ll, wr, ll);
                v = fmaf(bot - top, hr, top);
            }
            cur[j] = v;
        }

        if (i > 0) {
            float* o = out + (((size_t)n * CH + c) * 7 + (i - 1)) * 7;
            #pragma unroll
            for (int j = 0; j < 7; j++)
                o[j] = 0.25f * (prev[j] + prev[j + 1] + cur[j] + cur[j + 1]);
        }
        #pragma unroll
        for (int j = 0; j < PW; j++) prev[j] = cur[j];
    }
}

// ---------------------------------------------------------------------------
extern "C" void kernel_launch(void* const* d_in, const int* in_sizes, int n_in,
                              void* d_out, int out_size) {
    const float* features = (const float*)d_in[0];
    const float* rois     = (const float*)d_in[1];
    float*       out      = (float*)d_out;
    const int n_rois = in_sizes[1] / 5;

    dim3 tgrid((HW + 31) / 32, CH / 32, BATCH);
    dim3 tblk(32, 8);
    transpose_nchw_nhwc<<<tgrid, tblk>>>(features);

    roi_plus_avg_kernel<<<n_rois, CH>>>(rois, out);
}

// round 2
// speedup vs baseline: 3.0671x; 3.0671x over previous
#include <cuda_runtime.h>
#include <cuda_bf16.h>

#define BATCH 2
#define CH 512
#define FH 50
#define FW 75
#define HW (FH * FW)          // 3750
#define PH 8
#define PW 8
#define OUT_PER_ROI (CH * 7 * 7)          // 25088 floats
#define SMEM_BYTES (OUT_PER_ROI * 4)      // 100352 bytes
#define SPATIAL_SCALE (1.0f / 16.0f)

// NHWC scratch: 2 * 3750 * 512 floats = 15.36 MB (fits L2)
__device__ float g_feat_hwc[BATCH * HW * CH];

// ---------------------------------------------------------------------------
// Kernel 1: NCHW -> NHWC transpose.  Per batch: (C=512, HW=3750) -> (HW, C).
// ---------------------------------------------------------------------------
__global__ void transpose_nchw_nhwc(const float* __restrict__ in) {
    __shared__ float tile[32][33];
    const int b   = blockIdx.z;
    const int hw0 = blockIdx.x * 32;
    const int c0  = blockIdx.y * 32;

    const float* src = in + (size_t)b * CH * HW;
    float*       dst = g_feat_hwc + (size_t)b * HW * CH;

    #pragma unroll
    for (int t = 0; t < 32; t += 8) {
        int c  = c0 + threadIdx.y + t;
        int hw = hw0 + threadIdx.x;
        if (hw < HW)
            tile[threadIdx.y + t][threadIdx.x] = src[(size_t)c * HW + hw];
    }
    __syncthreads();
    #pragma unroll
    for (int t = 0; t < 32; t += 8) {
        int hw = hw0 + threadIdx.y + t;
        int c  = c0 + threadIdx.x;
        if (hw < HW)
            dst[(size_t)hw * CH + c] = tile[threadIdx.x][threadIdx.y + t];
    }
}

// ---------------------------------------------------------------------------
// Kernel 2: one CTA per roi, 512 threads = one channel each.
// Bilinear samples row-by-row (two register rows), fused 2x2 avg pool.
// Output staged in dynamic smem in final (c,7,7) layout, then copied out
// with fully coalesced float4 stores.
// ---------------------------------------------------------------------------
__global__ __launch_bounds__(CH, 2)
void roi_plus_avg_kernel(const float* __restrict__ rois,
                         float* __restrict__ out) {
    extern __shared__ float s_out[];   // OUT_PER_ROI floats

    const int n = blockIdx.x;
    const int c = threadIdx.x;

    __shared__ int   s_hs[PH], s_ws[PW];
    __shared__ float s_hr[PH], s_wr[PW];
    __shared__ int   s_hv[PH], s_wv[PW];
    __shared__ int   s_b;

    if (threadIdx.x < PH) {
        const int i = threadIdx.x;
        const float x1 = rois[n * 5 + 1] * SPATIAL_SCALE;
        const float y1 = rois[n * 5 + 2] * SPATIAL_SCALE;
        const float x2 = rois[n * 5 + 3] * SPATIAL_SCALE;
        const float y2 = rois[n * 5 + 4] * SPATIAL_SCALE;
        const float roi_w = fmaxf(x2 - x1 + 1.0f, 0.0f);
        const float roi_h = fmaxf(y2 - y1 + 1.0f, 0.0f);
        const float bin_h = roi_h * (1.0f / (PH - 1));
        const float bin_w = roi_w * (1.0f / (PW - 1));

        const float hh = y1 + (float)i * bin_h;
        const float ww = x1 + (float)i * bin_w;

        s_hv[i] = (hh >= 0.0f) && (hh < (float)FH);
        s_wv[i] = (ww >= 0.0f) && (ww < (float)FW);

        int hs = (int)floorf(hh);
        int ws = (int)floorf(ww);
        hs = min(max(hs, 0), FH - 2);
        ws = min(max(ws, 0), FW - 2);
        s_hs[i] = hs;
        s_ws[i] = ws;
        s_hr[i] = hh - (float)hs;
        s_wr[i] = ww - (float)ws;

        if (i == 0) s_b = (int)rois[n * 5 + 0];
    }
    __syncthreads();

    const float* fb = g_feat_hwc + (size_t)s_b * HW * CH + c;

    float prev[PW];
    float cur[PW];

    #pragma unroll
    for (int i = 0; i < PH; i++) {
        const int   hs = s_hs[i];
        const float hr = s_hr[i];
        const bool  hv = (s_hv[i] != 0);
        const float* r0 = fb + (size_t)(hs * FW) * CH;
        const float* r1 = r0 + (size_t)FW * CH;

        #pragma unroll
        for (int j = 0; j < PW; j++) {
            float v = 0.0f;
            if (hv && s_wv[j]) {
                const int   ws = s_ws[j];
                const float wr = s_wr[j];
                const float ul = __ldg(r0 + (size_t)ws * CH);
                const float ur = __ldg(r0 + (size_t)(ws + 1) * CH);
                const float ll = __ldg(r1 + (size_t)ws * CH);
                const float lr = __ldg(r1 + (size_t)(ws + 1) * CH);
                const float top = fmaf(ur - ul, wr, ul);
                const float bot = fmaf(lr - ll, wr, ll);
                v = fmaf(bot - top, hr, top);
            }
            cur[j] = v;
        }

        if (i > 0) {
            // stage pooled row into smem in the exact global layout
            float* o = s_out + c * 49 + (i - 1) * 7;   // stride 49 (odd) -> no bank conflicts
            #pragma unroll
            for (int j = 0; j < 7; j++)
                o[j] = 0.25f * (prev[j] + prev[j + 1] + cur[j] + cur[j + 1]);
        }
        #pragma unroll
        for (int j = 0; j < PW; j++) prev[j] = cur[j];
    }

    __syncthreads();

    // Cooperative fully-coalesced copy-out: 25088 floats = 6272 float4
    float4*       dst4 = (float4*)(out + (size_t)n * OUT_PER_ROI);
    const float4* src4 = (const float4*)s_out;
    #pragma unroll 4
    for (int idx = threadIdx.x; idx < OUT_PER_ROI / 4; idx += CH)
        dst4[idx] = src4[idx];
}

// ---------------------------------------------------------------------------
extern "C" void kernel_launch(void* const* d_in, const int* in_sizes, int n_in,
                              void* d_out, int out_size) {
    const float* features = (const float*)d_in[0];
    const float* rois     = (const float*)d_in[1];
    float*       out      = (float*)d_out;
    const int n_rois = in_sizes[1] / 5;

    // Opt-in to >48KB dynamic smem (non-stream-ordered; capture-safe,
    // deterministic — called every launch).
    cudaFuncSetAttribute(roi_plus_avg_kernel,
                         cudaFuncAttributeMaxDynamicSharedMemorySize,
                         SMEM_BYTES);

    dim3 tgrid((HW + 31) / 32, CH / 32, BATCH);
    dim3 tblk(32, 8);
    transpose_nchw_nhwc<<<tgrid, tblk>>>(features);

    roi_plus_avg_kernel<<<n_rois, CH, SMEM_BYTES>>>(rois, out);
}

// round 3
// speedup vs baseline: 3.0740x; 1.0022x over previous
#include <cuda_runtime.h>
#include <cuda_bf16.h>

#define BATCH 2
#define CH 512
#define FH 50
#define FW 75
#define HW (FH * FW)          // 3750
#define PH 8
#define PW 8
#define OUT_PER_ROI (CH * 7 * 7)          // 25088 floats
#define SMEM_BYTES (OUT_PER_ROI * 4)      // 100352 bytes
#define SPATIAL_SCALE (1.0f / 16.0f)

// NHWC scratch: 2 * 3750 * 512 floats = 15.36 MB (fits L2)
__device__ float g_feat_hwc[BATCH * HW * CH];

// ---------------------------------------------------------------------------
// Kernel 1: NCHW -> NHWC transpose.  Per batch: (C=512, HW=3750) -> (HW, C).
// ---------------------------------------------------------------------------
__global__ void transpose_nchw_nhwc(const float* __restrict__ in) {
    __shared__ float tile[32][33];
    const int b   = blockIdx.z;
    const int hw0 = blockIdx.x * 32;
    const int c0  = blockIdx.y * 32;

    const float* src = in + (size_t)b * CH * HW;
    float*       dst = g_feat_hwc + (size_t)b * HW * CH;

    #pragma unroll
    for (int t = 0; t < 32; t += 8) {
        int c  = c0 + threadIdx.y + t;
        int hw = hw0 + threadIdx.x;
        if (hw < HW)
            tile[threadIdx.y + t][threadIdx.x] = src[(size_t)c * HW + hw];
    }
    __syncthreads();
    #pragma unroll
    for (int t = 0; t < 32; t += 8) {
        int hw = hw0 + threadIdx.y + t;
        int c  = c0 + threadIdx.x;
        if (hw < HW)
            dst[(size_t)hw * CH + c] = tile[threadIdx.x][threadIdx.y + t];
    }
}

// ---------------------------------------------------------------------------
// Kernel 2: one CTA per roi, 512 threads = one channel each.
// Bilinear samples row-by-row (two register rows), fused 2x2 avg pool.
// Output staged in dynamic smem in final (c,7,7) layout, then copied out
// with fully coalesced float4 stores.
// ---------------------------------------------------------------------------
__global__ __launch_bounds__(CH, 2)
void roi_plus_avg_kernel(const float* __restrict__ rois,
                         float* __restrict__ out) {
    extern __shared__ float s_out[];   // OUT_PER_ROI floats

    const int n = blockIdx.x;
    const int c = threadIdx.x;

    __shared__ int   s_hs[PH], s_ws[PW];
    __shared__ float s_hr[PH], s_wr[PW];
    __shared__ int   s_hv[PH], s_wv[PW];
    __shared__ int   s_b;

    if (threadIdx.x < PH) {
        const int i = threadIdx.x;
        const float x1 = rois[n * 5 + 1] * SPATIAL_SCALE;
        const float y1 = rois[n * 5 + 2] * SPATIAL_SCALE;
        const float x2 = rois[n * 5 + 3] * SPATIAL_SCALE;
        const float y2 = rois[n * 5 + 4] * SPATIAL_SCALE;
        const float roi_w = fmaxf(x2 - x1 + 1.0f, 0.0f);
        const float roi_h = fmaxf(y2 - y1 + 1.0f, 0.0f);
        const float bin_h = roi_h * (1.0f / (PH - 1));
        const float bin_w = roi_w * (1.0f / (PW - 1));

        const float hh = y1 + (float)i * bin_h;
        const float ww = x1 + (float)i * bin_w;

        s_hv[i] = (hh >= 0.0f) && (hh < (float)FH);
        s_wv[i] = (ww >= 0.0f) && (ww < (float)FW);

        int hs = (int)floorf(hh);
        int ws = (int)floorf(ww);
        hs = min(max(hs, 0), FH - 2);
        ws = min(max(ws, 0), FW - 2);
        s_hs[i] = hs;
        s_ws[i] = ws;
        s_hr[i] = hh - (float)hs;
        s_wr[i] = ww - (float)ws;

        if (i == 0) s_b = (int)rois[n * 5 + 0];
    }
    __syncthreads();

    const float* fb = g_feat_hwc + (size_t)s_b * HW * CH + c;

    float prev[PW];
    float cur[PW];

    #pragma unroll
    for (int i = 0; i < PH; i++) {
        const int   hs = s_hs[i];
        const float hr = s_hr[i];
        const bool  hv = (s_hv[i] != 0);
        const float* r0 = fb + (size_t)(hs * FW) * CH;
        const float* r1 = r0 + (size_t)FW * CH;

        #pragma unroll
        for (int j = 0; j < PW; j++) {
            float v = 0.0f;
            if (hv && s_wv[j]) {
                const int   ws = s_ws[j];
                const float wr = s_wr[j];
                const float ul = __ldg(r0 + (size_t)ws * CH);
                const float ur = __ldg(r0 + (size_t)(ws + 1) * CH);
                const float ll = __ldg(r1 + (size_t)ws * CH);
                const float lr = __ldg(r1 + (size_t)(ws + 1) * CH);
                const float top = fmaf(ur - ul, wr, ul);
                const float bot = fmaf(lr - ll, wr, ll);
                v = fmaf(bot - top, hr, top);
            }
            cur[j] = v;
        }

        if (i > 0) {
            // stage pooled row into smem in the exact global layout
            float* o = s_out + c * 49 + (i - 1) * 7;   // stride 49 (odd) -> no bank conflicts
            #pragma unroll
            for (int j = 0; j < 7; j++)
                o[j] = 0.25f * (prev[j] + prev[j + 1] + cur[j] + cur[j + 1]);
        }
        #pragma unroll
        for (int j = 0; j < PW; j++) prev[j] = cur[j];
    }

    __syncthreads();

    // Cooperative fully-coalesced copy-out: 25088 floats = 6272 float4
    float4*       dst4 = (float4*)(out + (size_t)n * OUT_PER_ROI);
    const float4* src4 = (const float4*)s_out;
    #pragma unroll 4
    for (int idx = threadIdx.x; idx < OUT_PER_ROI / 4; idx += CH)
        dst4[idx] = src4[idx];
}

// ---------------------------------------------------------------------------
extern "C" void kernel_launch(void* const* d_in, const int* in_sizes, int n_in,
                              void* d_out, int out_size) {
    const float* features = (const float*)d_in[0];
    const float* rois     = (const float*)d_in[1];
    float*       out      = (float*)d_out;
    const int n_rois = in_sizes[1] / 5;

    // Opt-in to >48KB dynamic smem (non-stream-ordered; capture-safe,
    // deterministic — called every launch).
    cudaFuncSetAttribute(roi_plus_avg_kernel,
                         cudaFuncAttributeMaxDynamicSharedMemorySize,
                         SMEM_BYTES);

    dim3 tgrid((HW + 31) / 32, CH / 32, BATCH);
    dim3 tblk(32, 8);
    transpose_nchw_nhwc<<<tgrid, tblk>>>(features);

    roi_plus_avg_kernel<<<n_rois, CH, SMEM_BYTES>>>(rois, out);
}